// round 3
// baseline (speedup 1.0000x reference)
#include <cuda_runtime.h>

#define T_TRIG 48
#define S_SPAN 128
#define NNODE  (T_TRIG * S_SPAN)     // 6144
#define DIM    128
#define NHEADS 4
#define HDIM   32
#define DEG    (S_SPAN + T_TRIG - 1) // 175

__device__ float g_h  [NNODE * DIM];
__device__ float g_A  [NNODE * NHEADS];
__device__ float g_B  [NNODE * NHEADS];
__device__ float g_m  [NNODE * NHEADS];
__device__ float g_rd [NNODE * NHEADS];
__device__ float g_tmp[NNODE * DIM];
__device__ float g_x1 [NNODE * DIM];

__device__ __forceinline__ float leaky02(float v) {
    return v > 0.f ? v : 0.2f * v;
}

// ---------------------------------------------------------------------------
// K1: h = x @ W + fused per-head attention dot products.
// 8 rows/block, 256 threads (128 cols x 2 row-groups of 4). grid = 768.
// ---------------------------------------------------------------------------
__global__ void __launch_bounds__(256)
k_gemm_attn(const float* __restrict__ x,
            const float* __restrict__ W,
            const float* __restrict__ att_src,
            const float* __restrict__ att_dst)
{
    __shared__ __align__(16) float xs[8 * 128];
    const int tid  = threadIdx.x;
    const int row0 = blockIdx.x * 8;

    ((float4*)xs)[tid] = ((const float4*)(x + row0 * 128))[tid];
    __syncthreads();

    const int col = tid & 127;
    const int rg  = tid >> 7;            // 0/1 -> rows rg*4 .. rg*4+3
    const float* xb = &xs[rg * 4 * 128];

    float acc[4] = {0.f, 0.f, 0.f, 0.f};

#pragma unroll 8
    for (int k4 = 0; k4 < 32; k4++) {
        const float w0 = W[(k4 * 4 + 0) * 128 + col];
        const float w1 = W[(k4 * 4 + 1) * 128 + col];
        const float w2 = W[(k4 * 4 + 2) * 128 + col];
        const float w3 = W[(k4 * 4 + 3) * 128 + col];
#pragma unroll
        for (int r = 0; r < 4; r++) {
            const float4 xv = *(const float4*)&xb[r * 128 + k4 * 4];
            acc[r] = fmaf(xv.x, w0, acc[r]);
            acc[r] = fmaf(xv.y, w1, acc[r]);
            acc[r] = fmaf(xv.z, w2, acc[r]);
            acc[r] = fmaf(xv.w, w3, acc[r]);
        }
    }

#pragma unroll
    for (int r = 0; r < 4; r++)
        g_h[(row0 + rg * 4 + r) * 128 + col] = acc[r];

    const int lane = tid & 31;
    const int head = (tid >> 5) & 3;     // warp's head == its col-chunk
    const float as = att_src[head * 32 + lane];
    const float ad = att_dst[head * 32 + lane];

#pragma unroll
    for (int r = 0; r < 4; r++) {
        float ps = acc[r] * as;
        float pd = acc[r] * ad;
#pragma unroll
        for (int o = 16; o; o >>= 1) {
            ps += __shfl_xor_sync(0xffffffffu, ps, o);
            pd += __shfl_xor_sync(0xffffffffu, pd, o);
        }
        if (lane == 0) {
            const int n = row0 + rg * 4 + r;
            g_A[n * 4 + head] = ps;
            g_B[n * 4 + head] = pd;
        }
    }
}

// ---------------------------------------------------------------------------
// K2: softmax stats per (dst node, head) over the 175 structured edges.
// One warp per (node, head). grid = N*4/8 blocks of 256 threads.
// ---------------------------------------------------------------------------
__global__ void __launch_bounds__(256)
k_stats()
{
    const int gw   = (blockIdx.x * blockDim.x + threadIdx.x) >> 5;
    const int lane = threadIdx.x & 31;
    const int n    = gw >> 2;
    const int head = gw & 3;
    const int r    = n >> 7;
    const int c    = n & 127;

    const float b = g_B[n * 4 + head];

    float vals[6];
    int   cnt = 0;
    float mx  = -1e30f;

    for (int e = lane; e < DEG; e += 32) {
        int src;
        if (e < S_SPAN) {
            src = r * S_SPAN + e;
        } else {
            int t = e - S_SPAN;
            t += (t >= r);
            src = t * S_SPAN + c;
        }
        float v = leaky02(g_A[src * 4 + head] + b);
        vals[cnt++] = v;
        mx = fmaxf(mx, v);
    }
#pragma unroll
    for (int o = 16; o; o >>= 1)
        mx = fmaxf(mx, __shfl_xor_sync(0xffffffffu, mx, o));

    float s = 0.f;
    for (int i = 0; i < cnt; i++) s += __expf(vals[i] - mx);
#pragma unroll
    for (int o = 16; o; o >>= 1)
        s += __shfl_xor_sync(0xffffffffu, s, o);

    if (lane == 0) {
        g_m[gw]  = mx;
        g_rd[gw] = 1.f / s;
    }
}

// ---------------------------------------------------------------------------
// K3: row aggregation. Block = (row r, head, c-quarter). grid = 48*4*4 = 768,
// 256 threads = 32 dst x 8 q-threads (4 dims each). Weights staged in shared.
// ---------------------------------------------------------------------------
__global__ void __launch_bounds__(256)
k_row_agg()
{
    const int b    = blockIdx.x;
    const int r    = b >> 4;
    const int head = (b >> 2) & 3;
    const int cq   = b & 3;

    __shared__ __align__(16) float Hs[128 * 36];
    __shared__ __align__(16) float ws[32 * 36];
    __shared__ float As[128];
    __shared__ float Bs[32], Ms[32], Rd[32];

    const int tid = threadIdx.x;

    // h slice for this (r, head): 128 src x 32 dims = 1024 float4
#pragma unroll
    for (int i = tid; i < 1024; i += 256) {
        const int cp = i >> 3, v = i & 7;
        const float4 val = *(const float4*)&g_h[(r * 128 + cp) * 128 + head * 32 + v * 4];
        *(float4*)&Hs[cp * 36 + v * 4] = val;
    }
    if (tid < 128) {
        As[tid] = g_A[(r * 128 + tid) * 4 + head];
    } else if (tid < 160) {
        Bs[tid - 128] = g_B [(r * 128 + cq * 32 + (tid - 128)) * 4 + head];
    } else if (tid < 192) {
        Ms[tid - 160] = g_m [(r * 128 + cq * 32 + (tid - 160)) * 4 + head];
    } else if (tid < 224) {
        Rd[tid - 192] = g_rd[(r * 128 + cq * 32 + (tid - 192)) * 4 + head];
    }
    __syncthreads();

    const int cl = tid >> 3;   // local dst 0..31
    const int q  = tid & 7;    // 4-dim slice

    float acc[4] = {0.f, 0.f, 0.f, 0.f};

    for (int cc = 0; cc < 4; cc++) {
        // stage 32 dst x 32 src weights, 4 per thread
#pragma unroll
        for (int i = 0; i < 4; i++) {
            const int k  = tid + 256 * i;
            const int wc = k >> 5, j = k & 31;
            const float v = leaky02(As[cc * 32 + j] + Bs[wc]);
            ws[wc * 36 + j] = __expf(v - Ms[wc]) * Rd[wc];
        }
        __syncthreads();

#pragma unroll
        for (int j = 0; j < 32; j++) {
            const float w = ws[cl * 36 + j];
            const float4 h = *(const float4*)&Hs[(cc * 32 + j) * 36 + q * 4];
            acc[0] = fmaf(w, h.x, acc[0]);
            acc[1] = fmaf(w, h.y, acc[1]);
            acc[2] = fmaf(w, h.z, acc[2]);
            acc[3] = fmaf(w, h.w, acc[3]);
        }
        __syncthreads();
    }

    const int base = (r * 128 + cq * 32 + cl) * 128 + head * 32 + q * 4;
    *(float4*)&g_tmp[base] = make_float4(acc[0], acc[1], acc[2], acc[3]);
}

// ---------------------------------------------------------------------------
// K4: column aggregation + row partial + bias + ELU.
// grid = 128 cols x 2 r-halves = 256, block = 768 = (24 r, 4 head, 8 q).
// Weights staged once in shared (ws, padded 49); Hs stored q-major so the
// warp's 32 float4 loads span all banks exactly once per phase.
// ---------------------------------------------------------------------------
__global__ void __launch_bounds__(768)
k_col_agg(const float* __restrict__ bias, float* __restrict__ out)
{
    const int c   = blockIdx.x >> 1;
    const int rh  = blockIdx.x & 1;
    const int tid = threadIdx.x;

    __shared__ __align__(16) float Hs[48 * 144];   // [t][q*16 + head*4 + e]
    __shared__ float ws[96 * 49];                  // [(rl*4+head)][t]
    __shared__ float Acol[48 * 4];
    __shared__ float Bs[96], Ms[96], Rd[96];
    __shared__ float bsh[128];

    // stage h for all 48 column sources (q-major layout)
#pragma unroll
    for (int i = tid; i < 1536; i += 768) {
        const int t = i >> 5, v = i & 31;          // v = dim/4
        const int hh = v >> 3, qq = v & 7;
        const float4 val = *(const float4*)&g_h[(t * 128 + c) * 128 + v * 4];
        *(float4*)&Hs[t * 144 + qq * 16 + hh * 4] = val;
    }
    if (tid < 192) {
        const int t = tid >> 2, hh = tid & 3;
        Acol[tid] = g_A[(t * 128 + c) * 4 + hh];
    } else if (tid < 288) {
        const int k  = tid - 192;
        const int rg = rh * 24 + (k >> 2), hh = k & 3;
        const int idx = (rg * 128 + c) * 4 + hh;
        Bs[k] = g_B[idx];
        Ms[k] = g_m[idx];
        Rd[k] = g_rd[idx];
    } else if (tid < 416) {
        bsh[tid - 288] = bias[tid - 288];
    }
    __syncthreads();

    // stage weights: 96 (rl,head) groups x 48 srcs, 6 per thread
    for (int i = tid; i < 96 * 48; i += 768) {
        const int g = i / 48, t = i - g * 48;
        const int hh = g & 3;
        const int rglob = rh * 24 + (g >> 2);
        const float v = leaky02(Acol[t * 4 + hh] + Bs[g]);
        float w = __expf(v - Ms[g]) * Rd[g];
        if (t == rglob) w = 0.f;
        ws[g * 49 + t] = w;
    }
    __syncthreads();

    const int rl   = tid >> 5;
    const int head = (tid >> 3) & 3;
    const int q    = tid & 7;
    const int g    = rl * 4 + head;
    const int rglob = rh * 24 + rl;

    float acc[4] = {0.f, 0.f, 0.f, 0.f};

#pragma unroll 6
    for (int t = 0; t < 48; t++) {
        const float w = ws[g * 49 + t];
        const float4 h = *(const float4*)&Hs[t * 144 + q * 16 + head * 4];
        acc[0] = fmaf(w, h.x, acc[0]);
        acc[1] = fmaf(w, h.y, acc[1]);
        acc[2] = fmaf(w, h.z, acc[2]);
        acc[3] = fmaf(w, h.w, acc[3]);
    }

    const int base = (rglob * 128 + c) * 128 + head * 32 + q * 4;
    const float4 t0 = *(const float4*)&g_tmp[base];
    const int bb = head * 32 + q * 4;

    float v0 = acc[0] + t0.x + bsh[bb + 0];
    float v1 = acc[1] + t0.y + bsh[bb + 1];
    float v2 = acc[2] + t0.z + bsh[bb + 2];
    float v3 = acc[3] + t0.w + bsh[bb + 3];
    v0 = v0 > 0.f ? v0 : (__expf(v0) - 1.f);
    v1 = v1 > 0.f ? v1 : (__expf(v1) - 1.f);
    v2 = v2 > 0.f ? v2 : (__expf(v2) - 1.f);
    v3 = v3 > 0.f ? v3 : (__expf(v3) - 1.f);

    *(float4*)&out[base] = make_float4(v0, v1, v2, v3);
}

// ---------------------------------------------------------------------------
static void run_layer(const float* x, const float* W, const float* asrc,
                      const float* adst, const float* bias, float* out)
{
    k_gemm_attn<<<NNODE / 8, 256>>>(x, W, asrc, adst);
    k_stats<<<(NNODE * NHEADS) / 8, 256>>>();
    k_row_agg<<<T_TRIG * NHEADS * 4, 256>>>();
    k_col_agg<<<S_SPAN * 2, 768>>>(bias, out);
}

extern "C" void kernel_launch(void* const* d_in, const int* in_sizes, int n_in,
                              void* d_out, int out_size)
{
    const float* x0  = (const float*)d_in[0];
    const float* W1  = (const float*)d_in[1];
    const float* as1 = (const float*)d_in[2];
    const float* ad1 = (const float*)d_in[3];
    const float* b1  = (const float*)d_in[4];
    const float* W2  = (const float*)d_in[5];
    const float* as2 = (const float*)d_in[6];
    const float* ad2 = (const float*)d_in[7];
    const float* b2  = (const float*)d_in[8];

    float* x1 = nullptr;
    cudaGetSymbolAddress((void**)&x1, g_x1);

    run_layer(x0, W1, as1, ad1, b1, x1);
    run_layer(x1, W2, as2, ad2, b2, (float*)d_out);
}

// round 4
// speedup vs baseline: 1.6269x; 1.6269x over previous
#include <cuda_runtime.h>

#define T_TRIG 48
#define S_SPAN 128
#define NNODE  (T_TRIG * S_SPAN)     // 6144
#define DIM    128
#define NHEADS 4
#define HDIM   32
#define DEG    (S_SPAN + T_TRIG - 1) // 175

__device__ float g_h  [NNODE * DIM];
__device__ float g_A  [NNODE * NHEADS];
__device__ float g_B  [NNODE * NHEADS];
__device__ float g_m  [NNODE * NHEADS];
__device__ float g_rd [NNODE * NHEADS];
__device__ float g_tmp[NNODE * DIM];
__device__ float g_x1 [NNODE * DIM];

__device__ __forceinline__ float leaky02(float v) {
    return v > 0.f ? v : 0.2f * v;
}

// ---------------------------------------------------------------------------
// K1: h = x @ W (6144x128 @ 128x128) + fused attention dot products.
// Tile M=32, N=128. 256 threads, thread = 4x4 register tile.
// Per 4 k-steps: 4 LDS.128 (x rows) + 4 LDG.128 (W) -> 64 FMA.
// grid = 192.
// ---------------------------------------------------------------------------
__global__ void __launch_bounds__(256)
k_gemm_attn(const float* __restrict__ x,
            const float* __restrict__ W,
            const float* __restrict__ att_src,
            const float* __restrict__ att_dst)
{
    __shared__ __align__(16) float xs[32 * 128];
    const int tid  = threadIdx.x;
    const int row0 = blockIdx.x * 32;

#pragma unroll
    for (int i = 0; i < 4; i++)
        ((float4*)xs)[tid + 256 * i] = ((const float4*)(x + row0 * 128))[tid + 256 * i];
    __syncthreads();

    const int ng = tid & 31;   // col group: cols ng*4..+3
    const int mg = tid >> 5;   // row group: rows mg*4..+3

    float acc[4][4];
#pragma unroll
    for (int r = 0; r < 4; r++)
#pragma unroll
        for (int c = 0; c < 4; c++) acc[r][c] = 0.f;

#pragma unroll 4
    for (int k4 = 0; k4 < 32; k4++) {
        float4 wv[4];
#pragma unroll
        for (int kk = 0; kk < 4; kk++)
            wv[kk] = __ldg((const float4*)&W[(k4 * 4 + kk) * 128 + ng * 4]);
#pragma unroll
        for (int r = 0; r < 4; r++) {
            const float4 xv = *(const float4*)&xs[(mg * 4 + r) * 128 + k4 * 4];
            acc[r][0] = fmaf(xv.x, wv[0].x, acc[r][0]);
            acc[r][1] = fmaf(xv.x, wv[0].y, acc[r][1]);
            acc[r][2] = fmaf(xv.x, wv[0].z, acc[r][2]);
            acc[r][3] = fmaf(xv.x, wv[0].w, acc[r][3]);
            acc[r][0] = fmaf(xv.y, wv[1].x, acc[r][0]);
            acc[r][1] = fmaf(xv.y, wv[1].y, acc[r][1]);
            acc[r][2] = fmaf(xv.y, wv[1].z, acc[r][2]);
            acc[r][3] = fmaf(xv.y, wv[1].w, acc[r][3]);
            acc[r][0] = fmaf(xv.z, wv[2].x, acc[r][0]);
            acc[r][1] = fmaf(xv.z, wv[2].y, acc[r][1]);
            acc[r][2] = fmaf(xv.z, wv[2].z, acc[r][2]);
            acc[r][3] = fmaf(xv.z, wv[2].w, acc[r][3]);
            acc[r][0] = fmaf(xv.w, wv[3].x, acc[r][0]);
            acc[r][1] = fmaf(xv.w, wv[3].y, acc[r][1]);
            acc[r][2] = fmaf(xv.w, wv[3].z, acc[r][2]);
            acc[r][3] = fmaf(xv.w, wv[3].w, acc[r][3]);
        }
    }

#pragma unroll
    for (int r = 0; r < 4; r++)
        *(float4*)&g_h[(row0 + mg * 4 + r) * 128 + ng * 4] =
            make_float4(acc[r][0], acc[r][1], acc[r][2], acc[r][3]);

    // attention dot products; head = ng>>3, 8 lanes per head
    const int head = ng >> 3;
    const float4 asv = *(const float4*)&att_src[head * 32 + (ng & 7) * 4];
    const float4 adv = *(const float4*)&att_dst[head * 32 + (ng & 7) * 4];

#pragma unroll
    for (int r = 0; r < 4; r++) {
        float ps = acc[r][0] * asv.x + acc[r][1] * asv.y + acc[r][2] * asv.z + acc[r][3] * asv.w;
        float pd = acc[r][0] * adv.x + acc[r][1] * adv.y + acc[r][2] * adv.z + acc[r][3] * adv.w;
#pragma unroll
        for (int o = 1; o < 8; o <<= 1) {
            ps += __shfl_xor_sync(0xffffffffu, ps, o);
            pd += __shfl_xor_sync(0xffffffffu, pd, o);
        }
        if ((ng & 7) == 0) {
            const int n = row0 + mg * 4 + r;
            g_A[n * 4 + head] = ps;
            g_B[n * 4 + head] = pd;
        }
    }
}

// ---------------------------------------------------------------------------
// K2: softmax stats per (dst node, head). One warp per (node, head).
// ---------------------------------------------------------------------------
__global__ void __launch_bounds__(256)
k_stats()
{
    const int gw   = (blockIdx.x * blockDim.x + threadIdx.x) >> 5;
    const int lane = threadIdx.x & 31;
    const int n    = gw >> 2;
    const int head = gw & 3;
    const int r    = n >> 7;
    const int c    = n & 127;

    const float b = g_B[n * 4 + head];

    float vals[6];
    int   cnt = 0;
    float mx  = -1e30f;

    for (int e = lane; e < DEG; e += 32) {
        int src;
        if (e < S_SPAN) {
            src = r * S_SPAN + e;
        } else {
            int t = e - S_SPAN;
            t += (t >= r);
            src = t * S_SPAN + c;
        }
        float v = leaky02(g_A[src * 4 + head] + b);
        vals[cnt++] = v;
        mx = fmaxf(mx, v);
    }
#pragma unroll
    for (int o = 16; o; o >>= 1)
        mx = fmaxf(mx, __shfl_xor_sync(0xffffffffu, mx, o));

    float s = 0.f;
    for (int i = 0; i < cnt; i++) s += __expf(vals[i] - mx);
#pragma unroll
    for (int o = 16; o; o >>= 1)
        s += __shfl_xor_sync(0xffffffffu, s, o);

    if (lane == 0) {
        g_m[gw]  = mx;
        g_rd[gw] = 1.f / s;
    }
}

// ---------------------------------------------------------------------------
// K3: row aggregation as GEMM C[64,32] = alpha[64,128] * H[128,32].
// Block = (r, head, c-half). grid = 48*4*2 = 384, 128 threads.
// Thread = 4 dst x 4 dims register tile. alpha staged transposed ws[src][dst]
// so per src j: 2 LDS.128 feed 16 FMA. Each exp computed once.
// ---------------------------------------------------------------------------
__global__ void __launch_bounds__(128)
k_row_agg()
{
    const int b    = blockIdx.x;
    const int r    = b >> 3;
    const int head = (b >> 2) & 1 ? 0 : 0; // placeholder (recomputed below)
    const int hh   = (b >> 1) & 3;
    const int ch   = b & 1;
    (void)head;

    __shared__ __align__(16) float Hs[128 * 36];
    __shared__ __align__(16) float ws[32 * 68];   // [src j][dst d], pad 68
    __shared__ float As[128];
    __shared__ float Bs[64], Ms[64], Rd[64];

    const int tid = threadIdx.x;

    // Hs: 128 src x 32 dims = 1024 float4, 8 per thread
#pragma unroll
    for (int i = tid; i < 1024; i += 128) {
        const int cp = i >> 3, v = i & 7;
        const float4 val = *(const float4*)&g_h[(r * 128 + cp) * 128 + hh * 32 + v * 4];
        *(float4*)&Hs[cp * 36 + v * 4] = val;
    }
    As[tid] = g_A[(r * 128 + tid) * 4 + hh];
    if (tid < 64) {
        const int idx = (r * 128 + ch * 64 + tid) * 4 + hh;
        Bs[tid] = g_B[idx];
        Rd[tid] = g_rd[idx];
    } else {
        const int idx = (r * 128 + ch * 64 + (tid - 64)) * 4 + hh;
        Ms[tid - 64] = g_m[idx];
    }
    __syncthreads();

    const int dg = tid >> 3;   // dst group (4 dsts), 0..15
    const int qg = tid & 7;    // dim group (4 dims)

    float acc[4][4];
#pragma unroll
    for (int a = 0; a < 4; a++)
#pragma unroll
        for (int e = 0; e < 4; e++) acc[a][e] = 0.f;

    for (int cc = 0; cc < 4; cc++) {
        // stage ws: 32 src x 64 dst, 16 per thread
#pragma unroll
        for (int i = tid; i < 2048; i += 128) {
            const int j = i >> 6, d = i & 63;
            const float v = leaky02(As[cc * 32 + j] + Bs[d]);
            ws[j * 68 + d] = __expf(v - Ms[d]) * Rd[d];
        }
        __syncthreads();

#pragma unroll
        for (int j = 0; j < 32; j++) {
            const float4 wv = *(const float4*)&ws[j * 68 + dg * 4];
            const float4 hv = *(const float4*)&Hs[(cc * 32 + j) * 36 + qg * 4];
            acc[0][0] = fmaf(wv.x, hv.x, acc[0][0]);
            acc[0][1] = fmaf(wv.x, hv.y, acc[0][1]);
            acc[0][2] = fmaf(wv.x, hv.z, acc[0][2]);
            acc[0][3] = fmaf(wv.x, hv.w, acc[0][3]);
            acc[1][0] = fmaf(wv.y, hv.x, acc[1][0]);
            acc[1][1] = fmaf(wv.y, hv.y, acc[1][1]);
            acc[1][2] = fmaf(wv.y, hv.z, acc[1][2]);
            acc[1][3] = fmaf(wv.y, hv.w, acc[1][3]);
            acc[2][0] = fmaf(wv.z, hv.x, acc[2][0]);
            acc[2][1] = fmaf(wv.z, hv.y, acc[2][1]);
            acc[2][2] = fmaf(wv.z, hv.z, acc[2][2]);
            acc[2][3] = fmaf(wv.z, hv.w, acc[2][3]);
            acc[3][0] = fmaf(wv.w, hv.x, acc[3][0]);
            acc[3][1] = fmaf(wv.w, hv.y, acc[3][1]);
            acc[3][2] = fmaf(wv.w, hv.z, acc[3][2]);
            acc[3][3] = fmaf(wv.w, hv.w, acc[3][3]);
        }
        __syncthreads();
    }

#pragma unroll
    for (int a = 0; a < 4; a++) {
        const int dst = ch * 64 + dg * 4 + a;
        *(float4*)&g_tmp[(r * 128 + dst) * 128 + hh * 32 + qg * 4] =
            make_float4(acc[a][0], acc[a][1], acc[a][2], acc[a][3]);
    }
}

// ---------------------------------------------------------------------------
// K4: column aggregation as GEMM C[48,128] = alpha[48,48] * H[48,128] (per
// head) + row partial + bias + ELU. Block per column c: grid = 128, 384 thr.
// Thread = 4 r x 4 dims. Weights staged in 3 chunks of 16 t.
// ---------------------------------------------------------------------------
__global__ void __launch_bounds__(384)
k_col_agg(const float* __restrict__ bias, float* __restrict__ out)
{
    const int c   = blockIdx.x;
    const int tid = threadIdx.x;

    __shared__ __align__(16) float Hs[48 * 136];    // [t][dim], pad 136
    __shared__ __align__(16) float ws[16 * 224];    // [t_loc][hh*56 + r]
    __shared__ float Acol[192], Brc[192], Ms[192], Rd[192];
    __shared__ float bsh[128];

    // Hs: 48 t x 128 dims = 1536 float4, 4 per thread
#pragma unroll
    for (int i = tid; i < 1536; i += 384) {
        const int t = i >> 5, v = i & 31;
        const float4 val = *(const float4*)&g_h[(t * 128 + c) * 128 + v * 4];
        *(float4*)&Hs[t * 136 + v * 4] = val;
    }
    if (tid < 192) {
        const int t = tid >> 2, h = tid & 3;
        const int idx = (t * 128 + c) * 4 + h;
        Acol[tid] = g_A[idx];
        Brc[tid]  = g_B[idx];
    } else {
        const int k = tid - 192;
        const int t = k >> 2, h = k & 3;
        const int idx = (t * 128 + c) * 4 + h;
        Ms[k] = g_m[idx];
        Rd[k] = g_rd[idx];
    }
    if (tid < 128) bsh[tid] = bias[tid];
    __syncthreads();

    const int rg   = tid >> 5;          // 12 r-groups (warp = one rg)
    const int head = (tid >> 3) & 3;
    const int qg   = tid & 7;

    float acc[4][4];
#pragma unroll
    for (int a = 0; a < 4; a++)
#pragma unroll
        for (int e = 0; e < 4; e++) acc[a][e] = 0.f;

    for (int chunk = 0; chunk < 3; chunk++) {
        const int t0 = chunk * 16;
        // stage ws: 16 t x 4 head x 48 r = 3072, 8 per thread
#pragma unroll
        for (int i = tid; i < 3072; i += 384) {
            const int g  = i / 48;         // t_loc*4 + hh
            const int rr = i - g * 48;
            const int tl = g >> 2, h = g & 3;
            const int t  = t0 + tl;
            const float v = leaky02(Acol[t * 4 + h] + Brc[rr * 4 + h]);
            float w = __expf(v - Ms[rr * 4 + h]) * Rd[rr * 4 + h];
            if (t == rr) w = 0.f;
            ws[tl * 224 + h * 56 + rr] = w;
        }
        __syncthreads();

#pragma unroll
        for (int tl = 0; tl < 16; tl++) {
            const float4 wv = *(const float4*)&ws[tl * 224 + head * 56 + rg * 4];
            const float4 hv = *(const float4*)&Hs[(t0 + tl) * 136 + head * 32 + qg * 4];
            acc[0][0] = fmaf(wv.x, hv.x, acc[0][0]);
            acc[0][1] = fmaf(wv.x, hv.y, acc[0][1]);
            acc[0][2] = fmaf(wv.x, hv.z, acc[0][2]);
            acc[0][3] = fmaf(wv.x, hv.w, acc[0][3]);
            acc[1][0] = fmaf(wv.y, hv.x, acc[1][0]);
            acc[1][1] = fmaf(wv.y, hv.y, acc[1][1]);
            acc[1][2] = fmaf(wv.y, hv.z, acc[1][2]);
            acc[1][3] = fmaf(wv.y, hv.w, acc[1][3]);
            acc[2][0] = fmaf(wv.z, hv.x, acc[2][0]);
            acc[2][1] = fmaf(wv.z, hv.y, acc[2][1]);
            acc[2][2] = fmaf(wv.z, hv.z, acc[2][2]);
            acc[2][3] = fmaf(wv.z, hv.w, acc[2][3]);
            acc[3][0] = fmaf(wv.w, hv.x, acc[3][0]);
            acc[3][1] = fmaf(wv.w, hv.y, acc[3][1]);
            acc[3][2] = fmaf(wv.w, hv.z, acc[3][2]);
            acc[3][3] = fmaf(wv.w, hv.w, acc[3][3]);
        }
        __syncthreads();
    }

    const int bb = head * 32 + qg * 4;
    const float4 bv = *(const float4*)&bsh[bb];
#pragma unroll
    for (int a = 0; a < 4; a++) {
        const int r = rg * 4 + a;
        const int base = (r * 128 + c) * 128 + bb;
        const float4 tv = *(const float4*)&g_tmp[base];
        float v0 = acc[a][0] + tv.x + bv.x;
        float v1 = acc[a][1] + tv.y + bv.y;
        float v2 = acc[a][2] + tv.z + bv.z;
        float v3 = acc[a][3] + tv.w + bv.w;
        v0 = v0 > 0.f ? v0 : (__expf(v0) - 1.f);
        v1 = v1 > 0.f ? v1 : (__expf(v1) - 1.f);
        v2 = v2 > 0.f ? v2 : (__expf(v2) - 1.f);
        v3 = v3 > 0.f ? v3 : (__expf(v3) - 1.f);
        *(float4*)&out[base] = make_float4(v0, v1, v2, v3);
    }
}

// ---------------------------------------------------------------------------
static void run_layer(const float* x, const float* W, const float* asrc,
                      const float* adst, const float* bias, float* out)
{
    k_gemm_attn<<<NNODE / 32, 256>>>(x, W, asrc, adst);
    k_stats<<<(NNODE * NHEADS) / 8, 256>>>();
    k_row_agg<<<T_TRIG * NHEADS * 2, 128>>>();
    k_col_agg<<<S_SPAN, 384>>>(bias, out);
}

extern "C" void kernel_launch(void* const* d_in, const int* in_sizes, int n_in,
                              void* d_out, int out_size)
{
    const float* x0  = (const float*)d_in[0];
    const float* W1  = (const float*)d_in[1];
    const float* as1 = (const float*)d_in[2];
    const float* ad1 = (const float*)d_in[3];
    const float* b1  = (const float*)d_in[4];
    const float* W2  = (const float*)d_in[5];
    const float* as2 = (const float*)d_in[6];
    const float* ad2 = (const float*)d_in[7];
    const float* b2  = (const float*)d_in[8];

    float* x1 = nullptr;
    cudaGetSymbolAddress((void**)&x1, g_x1);

    run_layer(x0, W1, as1, ad1, b1, x1);
    run_layer(x1, W2, as2, ad2, b2, (float*)d_out);
}

// round 5
// speedup vs baseline: 2.1051x; 1.2940x over previous
#include <cuda_runtime.h>

#define T_TRIG 48
#define S_SPAN 128
#define NNODE  (T_TRIG * S_SPAN)     // 6144
#define DIM    128
#define NHEADS 4
#define HDIM   32

__device__ float g_h   [NNODE * DIM];
__device__ float g_A   [NNODE * NHEADS];   // raw a_src
__device__ float g_B   [NNODE * NHEADS];   // raw a_dst
__device__ float g_EA  [NNODE * NHEADS];   // exp(A)
__device__ float g_EA5 [NNODE * NHEADS];   // exp(0.2 A)
__device__ float g_EB  [NNODE * NHEADS];   // exp(B)
__device__ float g_EB5 [NNODE * NHEADS];   // exp(0.2 B)
__device__ float g_srow[NNODE * NHEADS];   // row part of softmax denom
__device__ float g_tmp [NNODE * DIM];      // unnormalized row partial
__device__ float g_x1  [NNODE * DIM];

// ---------------------------------------------------------------------------
// K1: h = x @ W (6144x128 @ 128x128) + attention dots + the 4 exps per
// (node, head). Tile M=32,N=128; 256 threads; thread = 4x4 register tile.
// ---------------------------------------------------------------------------
__global__ void __launch_bounds__(256)
k_gemm_attn(const float* __restrict__ x,
            const float* __restrict__ W,
            const float* __restrict__ att_src,
            const float* __restrict__ att_dst)
{
    __shared__ __align__(16) float xs[32 * 128];
    const int tid  = threadIdx.x;
    const int row0 = blockIdx.x * 32;

#pragma unroll
    for (int i = 0; i < 4; i++)
        ((float4*)xs)[tid + 256 * i] = ((const float4*)(x + row0 * 128))[tid + 256 * i];
    __syncthreads();

    const int ng = tid & 31;
    const int mg = tid >> 5;

    float acc[4][4];
#pragma unroll
    for (int r = 0; r < 4; r++)
#pragma unroll
        for (int c = 0; c < 4; c++) acc[r][c] = 0.f;

#pragma unroll 4
    for (int k4 = 0; k4 < 32; k4++) {
        float4 wv[4];
#pragma unroll
        for (int kk = 0; kk < 4; kk++)
            wv[kk] = __ldg((const float4*)&W[(k4 * 4 + kk) * 128 + ng * 4]);
#pragma unroll
        for (int r = 0; r < 4; r++) {
            const float4 xv = *(const float4*)&xs[(mg * 4 + r) * 128 + k4 * 4];
            acc[r][0] = fmaf(xv.x, wv[0].x, acc[r][0]);
            acc[r][1] = fmaf(xv.x, wv[0].y, acc[r][1]);
            acc[r][2] = fmaf(xv.x, wv[0].z, acc[r][2]);
            acc[r][3] = fmaf(xv.x, wv[0].w, acc[r][3]);
            acc[r][0] = fmaf(xv.y, wv[1].x, acc[r][0]);
            acc[r][1] = fmaf(xv.y, wv[1].y, acc[r][1]);
            acc[r][2] = fmaf(xv.y, wv[1].z, acc[r][2]);
            acc[r][3] = fmaf(xv.y, wv[1].w, acc[r][3]);
            acc[r][0] = fmaf(xv.z, wv[2].x, acc[r][0]);
            acc[r][1] = fmaf(xv.z, wv[2].y, acc[r][1]);
            acc[r][2] = fmaf(xv.z, wv[2].z, acc[r][2]);
            acc[r][3] = fmaf(xv.z, wv[2].w, acc[r][3]);
            acc[r][0] = fmaf(xv.w, wv[3].x, acc[r][0]);
            acc[r][1] = fmaf(xv.w, wv[3].y, acc[r][1]);
            acc[r][2] = fmaf(xv.w, wv[3].z, acc[r][2]);
            acc[r][3] = fmaf(xv.w, wv[3].w, acc[r][3]);
        }
    }

#pragma unroll
    for (int r = 0; r < 4; r++)
        *(float4*)&g_h[(row0 + mg * 4 + r) * 128 + ng * 4] =
            make_float4(acc[r][0], acc[r][1], acc[r][2], acc[r][3]);

    const int head = ng >> 3;
    const float4 asv = *(const float4*)&att_src[head * 32 + (ng & 7) * 4];
    const float4 adv = *(const float4*)&att_dst[head * 32 + (ng & 7) * 4];

#pragma unroll
    for (int r = 0; r < 4; r++) {
        float ps = acc[r][0] * asv.x + acc[r][1] * asv.y + acc[r][2] * asv.z + acc[r][3] * asv.w;
        float pd = acc[r][0] * adv.x + acc[r][1] * adv.y + acc[r][2] * adv.z + acc[r][3] * adv.w;
#pragma unroll
        for (int o = 1; o < 8; o <<= 1) {
            ps += __shfl_xor_sync(0xffffffffu, ps, o);
            pd += __shfl_xor_sync(0xffffffffu, pd, o);
        }
        if ((ng & 7) == 0) {
            const int n = row0 + mg * 4 + r;
            const int i4 = n * 4 + head;
            g_A  [i4] = ps;
            g_B  [i4] = pd;
            g_EA [i4] = __expf(ps);
            g_EA5[i4] = __expf(0.2f * ps);
            g_EB [i4] = __expf(pd);
            g_EB5[i4] = __expf(0.2f * pd);
        }
    }
}

// ---------------------------------------------------------------------------
// K2: row aggregation (unnormalized) + row part of the softmax denominator.
// Block = (r, head, c-half). grid = 384, 128 threads.
// Weight = (A_j+B_c>0) ? EA_j*EB_c : EA5_j*EB5_c  -- no exp on the edge path.
// ---------------------------------------------------------------------------
__global__ void __launch_bounds__(128)
k_row_agg()
{
    const int b  = blockIdx.x;
    const int r  = b >> 3;
    const int hh = (b >> 1) & 3;
    const int ch = b & 1;

    __shared__ __align__(16) float Hs[128 * 36];
    __shared__ __align__(16) float ws[32 * 68];
    __shared__ float As[128], EAs[128], EA5s[128];
    __shared__ float Bs[64], EBs[64], EB5s[64];
    __shared__ float Ssum2[2][64];

    const int tid = threadIdx.x;

#pragma unroll
    for (int i = tid; i < 1024; i += 128) {
        const int cp = i >> 3, v = i & 7;
        *(float4*)&Hs[cp * 36 + v * 4] =
            *(const float4*)&g_h[(r * 128 + cp) * 128 + hh * 32 + v * 4];
    }
    {
        const int idx = (r * 128 + tid) * 4 + hh;
        As  [tid] = g_A  [idx];
        EAs [tid] = g_EA [idx];
        EA5s[tid] = g_EA5[idx];
    }
    if (tid < 64) {
        const int idx = (r * 128 + ch * 64 + tid) * 4 + hh;
        Bs  [tid] = g_B  [idx];
        EBs [tid] = g_EB [idx];
        EB5s[tid] = g_EB5[idx];
    }
    __syncthreads();

    const int d  = tid & 63;   // staging dst
    const int jh = tid >> 6;   // staging src half
    const float Bv   = Bs[d];
    const float EBv  = EBs[d];
    const float EB5v = EB5s[d];
    float srun = 0.f;

    const int dg = tid >> 3;
    const int qg = tid & 7;

    float acc[4][4];
#pragma unroll
    for (int a = 0; a < 4; a++)
#pragma unroll
        for (int e = 0; e < 4; e++) acc[a][e] = 0.f;

    for (int cc = 0; cc < 4; cc++) {
        // stage 32 src x 64 dst weights; thread owns (dst d, 16 srcs)
#pragma unroll
        for (int jj = 0; jj < 16; jj++) {
            const int j  = jh * 16 + jj;
            const int jx = cc * 32 + j;
            const float x = As[jx] + Bv;
            const float w = x > 0.f ? EAs[jx] * EBv : EA5s[jx] * EB5v;
            ws[j * 68 + d] = w;
            srun += w;
        }
        __syncthreads();

#pragma unroll
        for (int j = 0; j < 32; j++) {
            const float4 wv = *(const float4*)&ws[j * 68 + dg * 4];
            const float4 hv = *(const float4*)&Hs[(cc * 32 + j) * 36 + qg * 4];
            acc[0][0] = fmaf(wv.x, hv.x, acc[0][0]);
            acc[0][1] = fmaf(wv.x, hv.y, acc[0][1]);
            acc[0][2] = fmaf(wv.x, hv.z, acc[0][2]);
            acc[0][3] = fmaf(wv.x, hv.w, acc[0][3]);
            acc[1][0] = fmaf(wv.y, hv.x, acc[1][0]);
            acc[1][1] = fmaf(wv.y, hv.y, acc[1][1]);
            acc[1][2] = fmaf(wv.y, hv.z, acc[1][2]);
            acc[1][3] = fmaf(wv.y, hv.w, acc[1][3]);
            acc[2][0] = fmaf(wv.z, hv.x, acc[2][0]);
            acc[2][1] = fmaf(wv.z, hv.y, acc[2][1]);
            acc[2][2] = fmaf(wv.z, hv.z, acc[2][2]);
            acc[2][3] = fmaf(wv.z, hv.w, acc[2][3]);
            acc[3][0] = fmaf(wv.w, hv.x, acc[3][0]);
            acc[3][1] = fmaf(wv.w, hv.y, acc[3][1]);
            acc[3][2] = fmaf(wv.w, hv.z, acc[3][2]);
            acc[3][3] = fmaf(wv.w, hv.w, acc[3][3]);
        }
        __syncthreads();
    }

#pragma unroll
    for (int a = 0; a < 4; a++) {
        const int dst = ch * 64 + dg * 4 + a;
        *(float4*)&g_tmp[(r * 128 + dst) * 128 + hh * 32 + qg * 4] =
            make_float4(acc[a][0], acc[a][1], acc[a][2], acc[a][3]);
    }

    Ssum2[jh][d] = srun;
    __syncthreads();
    if (tid < 64)
        g_srow[(r * 128 + ch * 64 + tid) * 4 + hh] = Ssum2[0][tid] + Ssum2[1][tid];
}

// ---------------------------------------------------------------------------
// K3: column aggregation + denominator finalize + normalize + bias + ELU.
// Block per column c: grid = 128, 384 threads (12 rg x 4 head x 8 qg).
// ---------------------------------------------------------------------------
__global__ void __launch_bounds__(384)
k_col_agg(const float* __restrict__ bias, float* __restrict__ out)
{
    const int c   = blockIdx.x;
    const int tid = threadIdx.x;

    __shared__ __align__(16) float Hs[48 * 136];
    __shared__ __align__(16) float ws[16 * 224];
    __shared__ float Acol[192], EAc[192], EA5c[192];   // src (t, head)
    __shared__ float Brc[192], EBrc[192], EB5rc[192];  // dst (r, head)
    __shared__ float Srow[192], Rd[192];
    __shared__ float Sc2[2][192];
    __shared__ float bsh[128];

#pragma unroll
    for (int i = tid; i < 1536; i += 384) {
        const int t = i >> 5, v = i & 31;
        *(float4*)&Hs[t * 136 + v * 4] =
            *(const float4*)&g_h[(t * 128 + c) * 128 + v * 4];
    }
    if (tid < 192) {
        const int t = tid >> 2, h = tid & 3;
        const int idx = (t * 128 + c) * 4 + h;
        Acol [tid] = g_A   [idx];
        EAc  [tid] = g_EA  [idx];
        EA5c [tid] = g_EA5 [idx];
        Brc  [tid] = g_B   [idx];
        EBrc [tid] = g_EB  [idx];
        EB5rc[tid] = g_EB5 [idx];
        Srow [tid] = g_srow[idx];
    } else if (tid < 320) {
        bsh[tid - 192] = bias[tid - 192];
    }
    __syncthreads();

    // staging thread map: k = tid % 192 -> (rr, h); half selects 8 of 16 t's
    const int k    = tid < 192 ? tid : tid - 192;
    const int half = tid < 192 ? 0 : 1;
    const int rr   = k >> 2;
    const int h    = k & 3;
    const float Bv   = Brc[k];
    const float EBv  = EBrc[k];
    const float EB5v = EB5rc[k];
    float scrun = 0.f;

    const int rg   = tid >> 5;
    const int head = (tid >> 3) & 3;
    const int qg   = tid & 7;

    float acc[4][4];
#pragma unroll
    for (int a = 0; a < 4; a++)
#pragma unroll
        for (int e = 0; e < 4; e++) acc[a][e] = 0.f;

    for (int chunk = 0; chunk < 3; chunk++) {
        const int t0 = chunk * 16;
#pragma unroll
        for (int i = 0; i < 8; i++) {
            const int tl = half * 8 + i;
            const int t  = t0 + tl;
            const int sx = t * 4 + h;
            const float x = Acol[sx] + Bv;
            float w = x > 0.f ? EAc[sx] * EBv : EA5c[sx] * EB5v;
            if (t == rr) w = 0.f;
            ws[tl * 224 + h * 56 + rr] = w;
            scrun += w;
        }
        __syncthreads();

#pragma unroll
        for (int tl = 0; tl < 16; tl++) {
            const float4 wv = *(const float4*)&ws[tl * 224 + head * 56 + rg * 4];
            const float4 hv = *(const float4*)&Hs[(t0 + tl) * 136 + head * 32 + qg * 4];
            acc[0][0] = fmaf(wv.x, hv.x, acc[0][0]);
            acc[0][1] = fmaf(wv.x, hv.y, acc[0][1]);
            acc[0][2] = fmaf(wv.x, hv.z, acc[0][2]);
            acc[0][3] = fmaf(wv.x, hv.w, acc[0][3]);
            acc[1][0] = fmaf(wv.y, hv.x, acc[1][0]);
            acc[1][1] = fmaf(wv.y, hv.y, acc[1][1]);
            acc[1][2] = fmaf(wv.y, hv.z, acc[1][2]);
            acc[1][3] = fmaf(wv.y, hv.w, acc[1][3]);
            acc[2][0] = fmaf(wv.z, hv.x, acc[2][0]);
            acc[2][1] = fmaf(wv.z, hv.y, acc[2][1]);
            acc[2][2] = fmaf(wv.z, hv.z, acc[2][2]);
            acc[2][3] = fmaf(wv.z, hv.w, acc[2][3]);
            acc[3][0] = fmaf(wv.w, hv.x, acc[3][0]);
            acc[3][1] = fmaf(wv.w, hv.y, acc[3][1]);
            acc[3][2] = fmaf(wv.w, hv.z, acc[3][2]);
            acc[3][3] = fmaf(wv.w, hv.w, acc[3][3]);
        }
        __syncthreads();
    }

    Sc2[half][k] = scrun;
    __syncthreads();
    if (tid < 192)
        Rd[tid] = 1.f / (Srow[tid] + Sc2[0][tid] + Sc2[1][tid]);
    __syncthreads();

    const int bb = head * 32 + qg * 4;
    const float4 bv = *(const float4*)&bsh[bb];
#pragma unroll
    for (int a = 0; a < 4; a++) {
        const int r = rg * 4 + a;
        const float rd = Rd[r * 4 + head];
        const int base = (r * 128 + c) * 128 + bb;
        const float4 tv = *(const float4*)&g_tmp[base];
        float v0 = (acc[a][0] + tv.x) * rd + bv.x;
        float v1 = (acc[a][1] + tv.y) * rd + bv.y;
        float v2 = (acc[a][2] + tv.z) * rd + bv.z;
        float v3 = (acc[a][3] + tv.w) * rd + bv.w;
        v0 = v0 > 0.f ? v0 : (__expf(v0) - 1.f);
        v1 = v1 > 0.f ? v1 : (__expf(v1) - 1.f);
        v2 = v2 > 0.f ? v2 : (__expf(v2) - 1.f);
        v3 = v3 > 0.f ? v3 : (__expf(v3) - 1.f);
        *(float4*)&out[base] = make_float4(v0, v1, v2, v3);
    }
}

// ---------------------------------------------------------------------------
static void run_layer(const float* x, const float* W, const float* asrc,
                      const float* adst, const float* bias, float* out)
{
    k_gemm_attn<<<NNODE / 32, 256>>>(x, W, asrc, adst);
    k_row_agg<<<T_TRIG * NHEADS * 2, 128>>>();
    k_col_agg<<<S_SPAN, 384>>>(bias, out);
}

extern "C" void kernel_launch(void* const* d_in, const int* in_sizes, int n_in,
                              void* d_out, int out_size)
{
    const float* x0  = (const float*)d_in[0];
    const float* W1  = (const float*)d_in[1];
    const float* as1 = (const float*)d_in[2];
    const float* ad1 = (const float*)d_in[3];
    const float* b1  = (const float*)d_in[4];
    const float* W2  = (const float*)d_in[5];
    const float* as2 = (const float*)d_in[6];
    const float* ad2 = (const float*)d_in[7];
    const float* b2  = (const float*)d_in[8];

    float* x1 = nullptr;
    cudaGetSymbolAddress((void**)&x1, g_x1);

    run_layer(x0, W1, as1, ad1, b1, x1);
    run_layer(x1, W2, as2, ad2, b2, (float*)d_out);
}